// round 5
// baseline (speedup 1.0000x reference)
#include <cuda_runtime.h>

#define NN   100000
#define INC  128
#define OUTC 200
#define EE   1600000

// Scratch (static __device__ — no runtime allocation allowed)
__device__ __align__(128) float g_dinv[NN];
__device__ __align__(128) float g_agg[(long long)NN * INC];
__device__ int g_is64;

// ---------------------------------------------------------------------------
// 0) dtype probe: harness marshals int64 refs as int32 (per harness docs), but
//    detect from data: int64 values < 2^31 have all odd 32-bit words == 0.
__global__ void k_probe(const unsigned* __restrict__ ei_words) {
    if (threadIdx.x == 0 && blockIdx.x == 0) {
        int is64 = 1;
        for (int i = 0; i < 64; i++)
            if (ei_words[2 * i + 1] != 0u) { is64 = 0; break; }
        g_is64 = is64;
    }
}

__device__ __forceinline__ int load_idx(const void* ei, long long pos) {
    // pos in [0, 2*EE): logical element index into the flattened edge_index
    if (g_is64) return (int)((const long long*)ei)[pos];
    return ((const int*)ei)[pos];
}

// ---------------------------------------------------------------------------
// 1) degree init: self-loop contributes 1 to every node's in-degree
__global__ void k_deg_init() {
    int v = blockIdx.x * blockDim.x + threadIdx.x;
    if (v < NN) g_dinv[v] = 1.0f;
}

// 2) degree count over edge destinations (edge_index[1] = second EE elements)
__global__ void k_deg_count(const void* __restrict__ ei) {
    int e = blockIdx.x * blockDim.x + threadIdx.x;
    if (e < EE) {
        int v = load_idx(ei, (long long)EE + e);
        atomicAdd(&g_dinv[v], 1.0f);
    }
}

// 3) dinv = rsqrt(deg); init agg[v] = dinv[v]^2 * x[v]  (self-loop message)
//    one warp per node, float4 per lane (32 * 4 = 128 channels)
__global__ void k_dinv_self(const float* __restrict__ x) {
    int gw   = (blockIdx.x * blockDim.x + threadIdx.x) >> 5;
    int lane = threadIdx.x & 31;
    if (gw >= NN) return;
    float di = 0.0f;
    if (lane == 0) {
        di = rsqrtf(g_dinv[gw]);
        g_dinv[gw] = di;
    }
    di = __shfl_sync(0xffffffffu, di, 0);
    float w = di * di;
    float4 t = ((const float4*)(x + (long long)gw * INC))[lane];
    float4 o;
    o.x = t.x * w; o.y = t.y * w; o.z = t.z * w; o.w = t.w * w;
    ((float4*)(g_agg + (long long)gw * INC))[lane] = o;
}

// 4) edge scatter: agg[v] += dinv[u]*dinv[v] * x[u]
//    one warp per edge; coalesced 512B gather (LDG.128) + 4 scalar REDs/lane.
__global__ void k_scatter(const void* __restrict__ ei,
                          const float* __restrict__ x) {
    int e    = (int)(((long long)blockIdx.x * blockDim.x + threadIdx.x) >> 5);
    int lane = threadIdx.x & 31;
    if (e >= EE) return;
    int u = load_idx(ei, e);                   // src
    int v = load_idx(ei, (long long)EE + e);   // dst
    float w = g_dinv[u] * g_dinv[v];
    float4 t = ((const float4*)(x + (long long)u * INC))[lane];
    float* dst = g_agg + (long long)v * INC + lane * 4;
    atomicAdd(dst + 0, t.x * w);
    atomicAdd(dst + 1, t.y * w);
    atomicAdd(dst + 2, t.z * w);
    atomicAdd(dst + 3, t.w * w);
}

// ---------------------------------------------------------------------------
// 5) fused GEMM: [mu | logstd] = agg @ [W1 | W2] + [b1 | b2]
//    Persistent blocks; both W matrices (128x400 fp32 = 200 KB) in smem.
//    Each active thread (250 of 256): 4 rows x 16 cols; the 16 cols are
//    4 float4 quarters at Wsm cols {0,100,200,300}+4*cg -> conflict-free
//    LDS.128, quarters 0,1 -> mu, quarters 2,3 -> logstd. float4 stores.
#define TROWS 40
#define APAD  132
#define NTILES (NN / TROWS)            /* 2500, exact */
#define WSM_FLOATS (INC * 400)         /* 51200 */
#define ASM_FLOATS (TROWS * APAD)      /* 5280  */
#define GEMM_SMEM  ((WSM_FLOATS + ASM_FLOATS) * 4)  /* 225920 B */

__global__ __launch_bounds__(256, 1) void k_gemm(
    const float* __restrict__ W1, const float* __restrict__ b1,
    const float* __restrict__ W2, const float* __restrict__ b2,
    float* __restrict__ out)
{
    extern __shared__ float sm[];
    float* Wsm = sm;                 // [128][400]
    float* Asm = sm + WSM_FLOATS;    // [40][132] (padded rows)
    int tid = threadIdx.x;

    // Stage W1|W2 into smem once (persistent kernel)
    for (int i = tid; i < WSM_FLOATS; i += 256) {
        int k = i / 400;
        int c = i - k * 400;
        Wsm[i] = (c < 200) ? W1[k * 200 + c] : W2[k * 200 + (c - 200)];
    }

    int rb = tid / 25;          // row-block 0..9 for active threads
    int cg = tid - rb * 25;     // col-group 0..24
    bool active = (tid < 250);

    // Preload bias quarters (b1, b2 are tiny; keep in registers)
    float bq[4][4];
    if (active) {
        #pragma unroll
        for (int j = 0; j < 4; j++) {
            const float* bb = (j < 2) ? b1 : b2;
            int base = (j & 1) * 100 + cg * 4;
            #pragma unroll
            for (int ci = 0; ci < 4; ci++) bq[j][ci] = bb[base + ci];
        }
    }

    float* mu = out;
    float* ls = out + (long long)NN * OUTC;
    __syncthreads();

    for (int tile = blockIdx.x; tile < NTILES; tile += gridDim.x) {
        int rowbase = tile * TROWS;

        // Stage agg tile (40 rows x 128) into padded smem
        for (int i = tid; i < TROWS * INC; i += 256) {
            int r = i >> 7;
            int k = i & 127;
            Asm[r * APAD + k] = g_agg[(long long)(rowbase + r) * INC + k];
        }
        __syncthreads();

        if (active) {
            float acc[4][4][4];   // [row][quarter][ci]
            #pragma unroll
            for (int rr = 0; rr < 4; rr++)
                #pragma unroll
                for (int j = 0; j < 4; j++)
                    #pragma unroll
                    for (int ci = 0; ci < 4; ci++) acc[rr][j][ci] = 0.0f;

            #pragma unroll 4
            for (int k = 0; k < INC; k++) {
                float av[4];
                #pragma unroll
                for (int rr = 0; rr < 4; rr++)
                    av[rr] = Asm[(rb * 4 + rr) * APAD + k];
                float4 wv[4];
                #pragma unroll
                for (int j = 0; j < 4; j++)
                    wv[j] = *(const float4*)(Wsm + k * 400 + j * 100 + cg * 4);
                #pragma unroll
                for (int rr = 0; rr < 4; rr++) {
                    #pragma unroll
                    for (int j = 0; j < 4; j++) {
                        acc[rr][j][0] = fmaf(av[rr], wv[j].x, acc[rr][j][0]);
                        acc[rr][j][1] = fmaf(av[rr], wv[j].y, acc[rr][j][1]);
                        acc[rr][j][2] = fmaf(av[rr], wv[j].z, acc[rr][j][2]);
                        acc[rr][j][3] = fmaf(av[rr], wv[j].w, acc[rr][j][3]);
                    }
                }
            }

            // Vectorized stores: quarters 0,1 -> mu cols {0,100}+4cg; 2,3 -> logstd
            #pragma unroll
            for (int rr = 0; rr < 4; rr++) {
                long long r = rowbase + rb * 4 + rr;
                #pragma unroll
                for (int j = 0; j < 4; j++) {
                    float4 o;
                    o.x = acc[rr][j][0] + bq[j][0];
                    o.y = acc[rr][j][1] + bq[j][1];
                    o.z = acc[rr][j][2] + bq[j][2];
                    o.w = acc[rr][j][3] + bq[j][3];
                    float* base = (j < 2) ? mu : ls;
                    long long off = r * OUTC + (long long)((j & 1) * 100 + cg * 4);
                    *(float4*)(base + off) = o;
                }
            }
        }
        __syncthreads();
    }
}

// ---------------------------------------------------------------------------
extern "C" void kernel_launch(void* const* d_in, const int* in_sizes, int n_in,
                              void* d_out, int out_size) {
    const float* x  = (const float*)d_in[0];
    const void*  ei = d_in[1];
    const float* W1 = (const float*)d_in[2];
    const float* b1 = (const float*)d_in[3];
    const float* W2 = (const float*)d_in[4];
    const float* b2 = (const float*)d_in[5];
    float*       out = (float*)d_out;

    k_probe<<<1, 32>>>((const unsigned*)ei);
    k_deg_init<<<(NN + 255) / 256, 256>>>();
    k_deg_count<<<(EE + 255) / 256, 256>>>(ei);
    k_dinv_self<<<(NN * 32 + 255) / 256, 256>>>(x);            // warp/node
    k_scatter<<<(int)(((long long)EE * 32 + 255) / 256), 256>>>(ei, x); // warp/edge

    cudaFuncSetAttribute(k_gemm, cudaFuncAttributeMaxDynamicSharedMemorySize,
                         GEMM_SMEM);
    k_gemm<<<148, 256, GEMM_SMEM>>>(W1, b1, W2, b2, out);
}

// round 6
// speedup vs baseline: 1.4177x; 1.4177x over previous
#include <cuda_runtime.h>

#define NN   100000
#define INC  128
#define OUTC 200
#define EE   1600000

// Scratch (static __device__ — no runtime allocation allowed)
__device__ __align__(128) float g_dinv[NN];
__device__ __align__(128) float g_agg[(long long)NN * INC];
__device__ int g_is64;

// ---------------------------------------------------------------------------
// 0) dtype probe: harness marshals int64 refs as int32 (confirmed R5), but
//    keep the data-driven detection as insurance (P[false trigger] ~ 0).
__global__ void k_probe(const unsigned* __restrict__ ei_words) {
    if (threadIdx.x == 0 && blockIdx.x == 0) {
        int is64 = 1;
        for (int i = 0; i < 64; i++)
            if (ei_words[2 * i + 1] != 0u) { is64 = 0; break; }
        g_is64 = is64;
    }
}

__device__ __forceinline__ int load_idx(const void* ei, long long pos) {
    if (g_is64) return (int)((const long long*)ei)[pos];
    return ((const int*)ei)[pos];
}

// ---------------------------------------------------------------------------
// 1) degree init: self-loop contributes 1 to every node's in-degree
__global__ void k_deg_init() {
    int v = blockIdx.x * blockDim.x + threadIdx.x;
    if (v < NN) g_dinv[v] = 1.0f;
}

// 2) degree count over edge destinations (edge_index[1] = second EE elements)
__global__ void k_deg_count(const void* __restrict__ ei) {
    int e = blockIdx.x * blockDim.x + threadIdx.x;
    if (e < EE) {
        int v = load_idx(ei, (long long)EE + e);
        atomicAdd(&g_dinv[v], 1.0f);
    }
}

// 3) dinv = rsqrt(deg); init agg[v] = dinv[v]^2 * x[v]  (self-loop message)
__global__ void k_dinv_self(const float* __restrict__ x) {
    int gw   = (blockIdx.x * blockDim.x + threadIdx.x) >> 5;
    int lane = threadIdx.x & 31;
    if (gw >= NN) return;
    float di = 0.0f;
    if (lane == 0) {
        di = rsqrtf(g_dinv[gw]);
        g_dinv[gw] = di;
    }
    di = __shfl_sync(0xffffffffu, di, 0);
    float w = di * di;
    float4 t = ((const float4*)(x + (long long)gw * INC))[lane];
    float4 o;
    o.x = t.x * w; o.y = t.y * w; o.z = t.z * w; o.w = t.w * w;
    ((float4*)(g_agg + (long long)gw * INC))[lane] = o;
}

// 4) edge scatter: agg[v] += dinv[u]*dinv[v] * x[u]
//    one warp per edge; coalesced 512B gather (LDG.128) + ONE 16B vector RED
//    per lane. Vector RED is safe now that addresses are valid (R5 post-mortem:
//    the R3 trap was a wild generic address, not the instruction).
__global__ void k_scatter(const void* __restrict__ ei,
                          const float* __restrict__ x) {
    int e    = (int)(((long long)blockIdx.x * blockDim.x + threadIdx.x) >> 5);
    int lane = threadIdx.x & 31;
    if (e >= EE) return;
    int u = load_idx(ei, e);                   // src
    int v = load_idx(ei, (long long)EE + e);   // dst
    float w = g_dinv[u] * g_dinv[v];
    float4 t = ((const float4*)(x + (long long)u * INC))[lane];
    float* dst = g_agg + (long long)v * INC + lane * 4;
    asm volatile("red.global.add.v4.f32 [%0], {%1, %2, %3, %4};"
                 :: "l"(dst), "f"(t.x * w), "f"(t.y * w), "f"(t.z * w), "f"(t.w * w)
                 : "memory");
}

// ---------------------------------------------------------------------------
// 5) fused GEMM: [mu | logstd] = agg @ [W1 | W2] + [b1 | b2]  (unchanged)
#define TROWS 40
#define APAD  132
#define NTILES (NN / TROWS)            /* 2500, exact */
#define WSM_FLOATS (INC * 400)         /* 51200 */
#define ASM_FLOATS (TROWS * APAD)      /* 5280  */
#define GEMM_SMEM  ((WSM_FLOATS + ASM_FLOATS) * 4)  /* 225920 B */

__global__ __launch_bounds__(256, 1) void k_gemm(
    const float* __restrict__ W1, const float* __restrict__ b1,
    const float* __restrict__ W2, const float* __restrict__ b2,
    float* __restrict__ out)
{
    extern __shared__ float sm[];
    float* Wsm = sm;                 // [128][400]
    float* Asm = sm + WSM_FLOATS;    // [40][132] (padded rows)
    int tid = threadIdx.x;

    for (int i = tid; i < WSM_FLOATS; i += 256) {
        int k = i / 400;
        int c = i - k * 400;
        Wsm[i] = (c < 200) ? W1[k * 200 + c] : W2[k * 200 + (c - 200)];
    }

    int rb = tid / 25;          // row-block 0..9 for active threads
    int cg = tid - rb * 25;     // col-group 0..24
    bool active = (tid < 250);

    float bq[4][4];
    if (active) {
        #pragma unroll
        for (int j = 0; j < 4; j++) {
            const float* bb = (j < 2) ? b1 : b2;
            int base = (j & 1) * 100 + cg * 4;
            #pragma unroll
            for (int ci = 0; ci < 4; ci++) bq[j][ci] = bb[base + ci];
        }
    }

    float* mu = out;
    float* ls = out + (long long)NN * OUTC;
    __syncthreads();

    for (int tile = blockIdx.x; tile < NTILES; tile += gridDim.x) {
        int rowbase = tile * TROWS;

        for (int i = tid; i < TROWS * INC; i += 256) {
            int r = i >> 7;
            int k = i & 127;
            Asm[r * APAD + k] = g_agg[(long long)(rowbase + r) * INC + k];
        }
        __syncthreads();

        if (active) {
            float acc[4][4][4];   // [row][quarter][ci]
            #pragma unroll
            for (int rr = 0; rr < 4; rr++)
                #pragma unroll
                for (int j = 0; j < 4; j++)
                    #pragma unroll
                    for (int ci = 0; ci < 4; ci++) acc[rr][j][ci] = 0.0f;

            #pragma unroll 4
            for (int k = 0; k < INC; k++) {
                float av[4];
                #pragma unroll
                for (int rr = 0; rr < 4; rr++)
                    av[rr] = Asm[(rb * 4 + rr) * APAD + k];
                float4 wv[4];
                #pragma unroll
                for (int j = 0; j < 4; j++)
                    wv[j] = *(const float4*)(Wsm + k * 400 + j * 100 + cg * 4);
                #pragma unroll
                for (int rr = 0; rr < 4; rr++) {
                    #pragma unroll
                    for (int j = 0; j < 4; j++) {
                        acc[rr][j][0] = fmaf(av[rr], wv[j].x, acc[rr][j][0]);
                        acc[rr][j][1] = fmaf(av[rr], wv[j].y, acc[rr][j][1]);
                        acc[rr][j][2] = fmaf(av[rr], wv[j].z, acc[rr][j][2]);
                        acc[rr][j][3] = fmaf(av[rr], wv[j].w, acc[rr][j][3]);
                    }
                }
            }

            #pragma unroll
            for (int rr = 0; rr < 4; rr++) {
                long long r = rowbase + rb * 4 + rr;
                #pragma unroll
                for (int j = 0; j < 4; j++) {
                    float4 o;
                    o.x = acc[rr][j][0] + bq[j][0];
                    o.y = acc[rr][j][1] + bq[j][1];
                    o.z = acc[rr][j][2] + bq[j][2];
                    o.w = acc[rr][j][3] + bq[j][3];
                    float* base = (j < 2) ? mu : ls;
                    long long off = r * OUTC + (long long)((j & 1) * 100 + cg * 4);
                    *(float4*)(base + off) = o;
                }
            }
        }
        __syncthreads();
    }
}

// ---------------------------------------------------------------------------
extern "C" void kernel_launch(void* const* d_in, const int* in_sizes, int n_in,
                              void* d_out, int out_size) {
    const float* x  = (const float*)d_in[0];
    const void*  ei = d_in[1];
    const float* W1 = (const float*)d_in[2];
    const float* b1 = (const float*)d_in[3];
    const float* W2 = (const float*)d_in[4];
    const float* b2 = (const float*)d_in[5];
    float*       out = (float*)d_out;

    k_probe<<<1, 32>>>((const unsigned*)ei);
    k_deg_init<<<(NN + 255) / 256, 256>>>();
    k_deg_count<<<(EE + 255) / 256, 256>>>(ei);
    k_dinv_self<<<(NN * 32 + 255) / 256, 256>>>(x);            // warp/node
    k_scatter<<<(int)(((long long)EE * 32 + 255) / 256), 256>>>(ei, x); // warp/edge

    cudaFuncSetAttribute(k_gemm, cudaFuncAttributeMaxDynamicSharedMemorySize,
                         GEMM_SMEM);
    k_gemm<<<148, 256, GEMM_SMEM>>>(W1, b1, W2, b2, out);
}

// round 7
// speedup vs baseline: 1.4519x; 1.0241x over previous
#include <cuda_runtime.h>

#define NN   100000
#define INC  128
#define OUTC 200
#define EE   1600000

typedef unsigned long long u64;

// Scratch (static __device__ — no runtime allocation allowed)
__device__ __align__(128) float g_dinv[NN];
__device__ __align__(128) float g_agg[(long long)NN * INC];
__device__ int g_is64;

// ---------------------------------------------------------------------------
// f32x2 packed-math helpers (Blackwell; FFMA2 reachable only via PTX)
__device__ __forceinline__ u64 pack2(float lo, float hi) {
    u64 r; asm("mov.b64 %0, {%1, %2};" : "=l"(r) : "f"(lo), "f"(hi)); return r;
}
__device__ __forceinline__ void fma2(u64& d, u64 a, u64 b) {
    asm("fma.rn.f32x2 %0, %1, %2, %0;" : "+l"(d) : "l"(a), "l"(b));
}
__device__ __forceinline__ u64 add2(u64 a, u64 b) {
    u64 r; asm("add.rn.f32x2 %0, %1, %2;" : "=l"(r) : "l"(a), "l"(b)); return r;
}
__device__ __forceinline__ void unpack2(u64 v, float& lo, float& hi) {
    asm("mov.b64 {%0, %1}, %2;" : "=f"(lo), "=f"(hi) : "l"(v));
}

// ---------------------------------------------------------------------------
// 0) dtype probe: harness marshals int64 refs as int32 (confirmed R5); keep
//    data-driven detection as insurance.
__global__ void k_probe(const unsigned* __restrict__ ei_words) {
    if (threadIdx.x == 0 && blockIdx.x == 0) {
        int is64 = 1;
        for (int i = 0; i < 64; i++)
            if (ei_words[2 * i + 1] != 0u) { is64 = 0; break; }
        g_is64 = is64;
    }
}

__device__ __forceinline__ int load_idx(const void* ei, long long pos) {
    if (g_is64) return (int)((const long long*)ei)[pos];
    return ((const int*)ei)[pos];
}

// ---------------------------------------------------------------------------
// 1) degree init: self-loop contributes 1 to every node's in-degree
__global__ void k_deg_init() {
    int v = blockIdx.x * blockDim.x + threadIdx.x;
    if (v < NN) g_dinv[v] = 1.0f;
}

// 2) degree count over edge destinations
__global__ void k_deg_count(const void* __restrict__ ei) {
    int e = blockIdx.x * blockDim.x + threadIdx.x;
    if (e < EE) {
        int v = load_idx(ei, (long long)EE + e);
        atomicAdd(&g_dinv[v], 1.0f);
    }
}

// 3) dinv = rsqrt(deg); init agg[v] = dinv[v]^2 * x[v]  (self-loop message)
__global__ void k_dinv_self(const float* __restrict__ x) {
    int gw   = (blockIdx.x * blockDim.x + threadIdx.x) >> 5;
    int lane = threadIdx.x & 31;
    if (gw >= NN) return;
    float di = 0.0f;
    if (lane == 0) {
        di = rsqrtf(g_dinv[gw]);
        g_dinv[gw] = di;
    }
    di = __shfl_sync(0xffffffffu, di, 0);
    float w = di * di;
    float4 t = ((const float4*)(x + (long long)gw * INC))[lane];
    float4 o;
    o.x = t.x * w; o.y = t.y * w; o.z = t.z * w; o.w = t.w * w;
    ((float4*)(g_agg + (long long)gw * INC))[lane] = o;
}

// 4) edge scatter: agg[v] += dinv[u]*dinv[v] * x[u]
//    one warp per edge; coalesced 512B gather (LDG.128) + ONE 16B vector RED.
__global__ void k_scatter(const void* __restrict__ ei,
                          const float* __restrict__ x) {
    int e    = (int)(((long long)blockIdx.x * blockDim.x + threadIdx.x) >> 5);
    int lane = threadIdx.x & 31;
    if (e >= EE) return;
    int u = load_idx(ei, e);                   // src
    int v = load_idx(ei, (long long)EE + e);   // dst
    float w = g_dinv[u] * g_dinv[v];
    float4 t = ((const float4*)(x + (long long)u * INC))[lane];
    float* dst = g_agg + (long long)v * INC + lane * 4;
    asm volatile("red.global.add.v4.f32 [%0], {%1, %2, %3, %4};"
                 :: "l"(dst), "f"(t.x * w), "f"(t.y * w), "f"(t.z * w), "f"(t.w * w)
                 : "memory");
}

// ---------------------------------------------------------------------------
// 5) fused GEMM: [mu | logstd] = agg @ [W1 | W2] + [b1 | b2]
//    Same tiling as R6 (both W in smem, persistent 148 CTAs, 250 active
//    threads doing 4 rows x 16 cols), but the inner product now runs on the
//    packed f32x2 pipe: wv float4 = 2 x f32x2 register pairs, A broadcast
//    packed {a,a}, accumulators u64. Halves the FMA-pipe instruction count.
#define TROWS 40
#define APAD  132
#define NTILES (NN / TROWS)            /* 2500, exact */
#define WSM_FLOATS (INC * 400)         /* 51200 */
#define ASM_FLOATS (TROWS * APAD)      /* 5280  */
#define GEMM_SMEM  ((WSM_FLOATS + ASM_FLOATS) * 4)  /* 225920 B */

__global__ __launch_bounds__(256, 1) void k_gemm(
    const float* __restrict__ W1, const float* __restrict__ b1,
    const float* __restrict__ W2, const float* __restrict__ b2,
    float* __restrict__ out)
{
    extern __shared__ float sm[];
    float* Wsm = sm;                 // [128][400]
    float* Asm = sm + WSM_FLOATS;    // [40][132] (padded rows)
    int tid = threadIdx.x;

    for (int i = tid; i < WSM_FLOATS; i += 256) {
        int k = i / 400;
        int c = i - k * 400;
        Wsm[i] = (c < 200) ? W1[k * 200 + c] : W2[k * 200 + (c - 200)];
    }

    int rb = tid / 25;          // row-block 0..9 for active threads
    int cg = tid - rb * 25;     // col-group 0..24
    bool active = (tid < 250);

    // Bias as packed f32x2 pairs
    u64 bq[4][2];
    if (active) {
        #pragma unroll
        for (int j = 0; j < 4; j++) {
            const float* bb = (j < 2) ? b1 : b2;
            int base = (j & 1) * 100 + cg * 4;
            bq[j][0] = pack2(bb[base + 0], bb[base + 1]);
            bq[j][1] = pack2(bb[base + 2], bb[base + 3]);
        }
    }

    float* mu = out;
    float* ls = out + (long long)NN * OUTC;
    __syncthreads();

    for (int tile = blockIdx.x; tile < NTILES; tile += gridDim.x) {
        int rowbase = tile * TROWS;

        for (int i = tid; i < TROWS * INC; i += 256) {
            int r = i >> 7;
            int k = i & 127;
            Asm[r * APAD + k] = g_agg[(long long)(rowbase + r) * INC + k];
        }
        __syncthreads();

        if (active) {
            u64 acc[4][4][2];   // [row][quarter][pair], each = 2 packed f32
            #pragma unroll
            for (int rr = 0; rr < 4; rr++)
                #pragma unroll
                for (int j = 0; j < 4; j++) {
                    acc[rr][j][0] = 0ull;
                    acc[rr][j][1] = 0ull;
                }

            #pragma unroll 4
            for (int k = 0; k < INC; k++) {
                u64 avp[4];
                #pragma unroll
                for (int rr = 0; rr < 4; rr++) {
                    float a = Asm[(rb * 4 + rr) * APAD + k];
                    avp[rr] = pack2(a, a);
                }
                ulonglong2 wv[4];
                #pragma unroll
                for (int j = 0; j < 4; j++)
                    wv[j] = *(const ulonglong2*)(Wsm + k * 400 + j * 100 + cg * 4);
                #pragma unroll
                for (int rr = 0; rr < 4; rr++) {
                    #pragma unroll
                    for (int j = 0; j < 4; j++) {
                        fma2(acc[rr][j][0], avp[rr], wv[j].x);
                        fma2(acc[rr][j][1], avp[rr], wv[j].y);
                    }
                }
            }

            #pragma unroll
            for (int rr = 0; rr < 4; rr++) {
                long long r = rowbase + rb * 4 + rr;
                #pragma unroll
                for (int j = 0; j < 4; j++) {
                    u64 p0 = add2(acc[rr][j][0], bq[j][0]);
                    u64 p1 = add2(acc[rr][j][1], bq[j][1]);
                    float4 o;
                    unpack2(p0, o.x, o.y);
                    unpack2(p1, o.z, o.w);
                    float* base = (j < 2) ? mu : ls;
                    long long off = r * OUTC + (long long)((j & 1) * 100 + cg * 4);
                    *(float4*)(base + off) = o;
                }
            }
        }
        __syncthreads();
    }
}

// ---------------------------------------------------------------------------
extern "C" void kernel_launch(void* const* d_in, const int* in_sizes, int n_in,
                              void* d_out, int out_size) {
    const float* x  = (const float*)d_in[0];
    const void*  ei = d_in[1];
    const float* W1 = (const float*)d_in[2];
    const float* b1 = (const float*)d_in[3];
    const float* W2 = (const float*)d_in[4];
    const float* b2 = (const float*)d_in[5];
    float*       out = (float*)d_out;

    k_probe<<<1, 32>>>((const unsigned*)ei);
    k_deg_init<<<(NN + 255) / 256, 256>>>();
    k_deg_count<<<(EE + 255) / 256, 256>>>(ei);
    k_dinv_self<<<(NN * 32 + 255) / 256, 256>>>(x);            // warp/node
    k_scatter<<<(int)(((long long)EE * 32 + 255) / 256), 256>>>(ei, x); // warp/edge

    cudaFuncSetAttribute(k_gemm, cudaFuncAttributeMaxDynamicSharedMemorySize,
                         GEMM_SMEM);
    k_gemm<<<148, 256, GEMM_SMEM>>>(W1, b1, W2, b2, out);
}

// round 8
// speedup vs baseline: 1.5224x; 1.0486x over previous
#include <cuda_runtime.h>

#define NN   100000
#define INC  128
#define OUTC 200
#define EE   1600000

typedef unsigned int u32;

// Scratch (static __device__ — no runtime allocation allowed)
__device__ __align__(128) float g_dinv[NN];
__device__ __align__(128) float g_agg[(long long)NN * INC];
__device__ int g_is64;

// ---------------------------------------------------------------------------
// tf32 split helpers: a = hi + lo exactly (Dekker split via cvt.rna.tf32)
__device__ __forceinline__ void tf32_split(float a, u32& hi, u32& lo) {
    asm("cvt.rna.tf32.f32 %0, %1;" : "=r"(hi) : "f"(a));
    float res = a - __uint_as_float(hi);
    asm("cvt.rna.tf32.f32 %0, %1;" : "=r"(lo) : "f"(res));
}

__device__ __forceinline__ void mma_tf32(float* c, const u32* a, u32 b0, u32 b1) {
    asm("mma.sync.aligned.m16n8k8.row.col.f32.tf32.tf32.f32 "
        "{%0,%1,%2,%3}, {%4,%5,%6,%7}, {%8,%9}, {%0,%1,%2,%3};"
        : "+f"(c[0]), "+f"(c[1]), "+f"(c[2]), "+f"(c[3])
        : "r"(a[0]), "r"(a[1]), "r"(a[2]), "r"(a[3]), "r"(b0), "r"(b1));
}

// ---------------------------------------------------------------------------
// 1) degree init + dtype probe fused (also rotates ncu slot #4 onto k_scatter)
__global__ void k_deg_init(const unsigned* __restrict__ ei_words) {
    int v = blockIdx.x * blockDim.x + threadIdx.x;
    if (v < NN) g_dinv[v] = 1.0f;
    if (v == 0) {
        int is64 = 1;
        for (int i = 0; i < 64; i++)
            if (ei_words[2 * i + 1] != 0u) { is64 = 0; break; }
        g_is64 = is64;
    }
}

__device__ __forceinline__ int load_idx(const void* ei, long long pos) {
    if (g_is64) return (int)((const long long*)ei)[pos];
    return ((const int*)ei)[pos];
}

// 2) degree count over edge destinations
__global__ void k_deg_count(const void* __restrict__ ei) {
    int e = blockIdx.x * blockDim.x + threadIdx.x;
    if (e < EE) {
        int v = load_idx(ei, (long long)EE + e);
        atomicAdd(&g_dinv[v], 1.0f);
    }
}

// 3) dinv = rsqrt(deg); init agg[v] = dinv[v]^2 * x[v]  (self-loop message)
__global__ void k_dinv_self(const float* __restrict__ x) {
    int gw   = (blockIdx.x * blockDim.x + threadIdx.x) >> 5;
    int lane = threadIdx.x & 31;
    if (gw >= NN) return;
    float di = 0.0f;
    if (lane == 0) {
        di = rsqrtf(g_dinv[gw]);
        g_dinv[gw] = di;
    }
    di = __shfl_sync(0xffffffffu, di, 0);
    float w = di * di;
    float4 t = ((const float4*)(x + (long long)gw * INC))[lane];
    float4 o;
    o.x = t.x * w; o.y = t.y * w; o.z = t.z * w; o.w = t.w * w;
    ((float4*)(g_agg + (long long)gw * INC))[lane] = o;
}

// 4) edge scatter: agg[v] += dinv[u]*dinv[v] * x[u]
//    one warp per edge; coalesced 512B gather (LDG.128) + ONE 16B vector RED.
__global__ void k_scatter(const void* __restrict__ ei,
                          const float* __restrict__ x) {
    int e    = (int)(((long long)blockIdx.x * blockDim.x + threadIdx.x) >> 5);
    int lane = threadIdx.x & 31;
    if (e >= EE) return;
    int u = load_idx(ei, e);                   // src
    int v = load_idx(ei, (long long)EE + e);   // dst
    float w = g_dinv[u] * g_dinv[v];
    float4 t = ((const float4*)(x + (long long)u * INC))[lane];
    float* dst = g_agg + (long long)v * INC + lane * 4;
    asm volatile("red.global.add.v4.f32 [%0], {%1, %2, %3, %4};"
                 :: "l"(dst), "f"(t.x * w), "f"(t.y * w), "f"(t.z * w), "f"(t.w * w)
                 : "memory");
}

// ---------------------------------------------------------------------------
// 5) tensor-core GEMM: [mu | logstd] = agg @ [W1 | W2] + [b1 | b2]
//    mma.sync m16n8k8 tf32 with 3-term split (rel err ~1e-7).
//    W staged in smem [128][408] (pad 8: B-frag rows land on disjoint bank
//    runs 0-7 / 24-31 / 16-23 / 8-15). A fragments read from L2-resident
//    g_agg. Per CTA: 64 rows x 400 cols; warp w: row-block (w&3)*16,
//    col-half (w>>2)*200 -> 25 n8-blocks, acc = 25x4 f32.
#define WPAD     408
#define WSM_FL   (INC * WPAD)                 /* 52224 floats */
#define GEMM_SMEM (WSM_FL * 4)                /* 208896 B */
#define MTILE    64
#define NTILES   ((NN + MTILE - 1) / MTILE)   /* 1563 (last partial: 32 rows) */

__global__ __launch_bounds__(256, 1) void k_gemm(
    const float* __restrict__ W1, const float* __restrict__ b1,
    const float* __restrict__ W2, const float* __restrict__ b2,
    float* __restrict__ out)
{
    extern __shared__ float Wsm[];   // [128][408]
    int tid = threadIdx.x;

    for (int i = tid; i < INC * 400; i += 256) {
        int k = i / 400;
        int c = i - k * 400;
        Wsm[k * WPAD + c] = (c < 200) ? W1[k * 200 + c] : W2[k * 200 + (c - 200)];
    }

    int wid  = tid >> 5;
    int lane = tid & 31;
    int g    = lane >> 2;     // group id: row within m16 / col within n8
    int tig  = lane & 3;      // thread-in-group: k index
    int rb   = wid & 3;       // row-block 0..3
    int n0w  = (wid >> 2) * 200;  // col-half base

    // Bias pairs for this thread's store columns (cols n0w+8*nb+2*tig, +1)
    float2 bias2[25];
    #pragma unroll
    for (int nb = 0; nb < 25; nb++) {
        int c = n0w + nb * 8 + 2 * tig;
        const float* bb = (c < 200) ? b1 : b2;
        int cc = (c < 200) ? c : c - 200;
        bias2[nb] = make_float2(bb[cc], bb[cc + 1]);
    }

    float* mu = out;
    float* ls = out + (long long)NN * OUTC;
    __syncthreads();

    for (int tile = blockIdx.x; tile < NTILES; tile += gridDim.x) {
        int r0 = tile * MTILE + rb * 16 + g;
        int r1 = r0 + 8;
        bool v0 = r0 < NN, v1 = r1 < NN;
        const float* arow0 = g_agg + (long long)(v0 ? r0 : 0) * INC;
        const float* arow1 = g_agg + (long long)(v1 ? r1 : 0) * INC;

        float acc[25][4];
        #pragma unroll
        for (int nb = 0; nb < 25; nb++)
            #pragma unroll
            for (int i = 0; i < 4; i++) acc[nb][i] = 0.0f;

        for (int k0 = 0; k0 < INC; k0 += 8) {
            // A fragment: a0(r0,k+tig) a1(r1,k+tig) a2(r0,k+tig+4) a3(r1,k+tig+4)
            float af[4];
            af[0] = arow0[k0 + tig];
            af[1] = arow1[k0 + tig];
            af[2] = arow0[k0 + tig + 4];
            af[3] = arow1[k0 + tig + 4];
            u32 ahi[4], alo[4];
            #pragma unroll
            for (int i = 0; i < 4; i++) tf32_split(af[i], ahi[i], alo[i]);

            const float* wk0 = Wsm + (k0 + tig) * WPAD;
            const float* wk1 = Wsm + (k0 + tig + 4) * WPAD;

            #pragma unroll
            for (int nb = 0; nb < 25; nb++) {
                int col = n0w + nb * 8 + g;
                float b0f = wk0[col];
                float b1f = wk1[col];
                u32 bh0, bl0, bh1, bl1;
                tf32_split(b0f, bh0, bl0);
                tf32_split(b1f, bh1, bl1);
                mma_tf32(acc[nb], ahi, bh0, bh1);   // hi*hi
                mma_tf32(acc[nb], ahi, bl0, bl1);   // hi*lo
                mma_tf32(acc[nb], alo, bh0, bh1);   // lo*hi
            }
        }

        // Stores: c0,c1 -> (r0, cbase..+1), c2,c3 -> (r1, cbase..+1)
        #pragma unroll
        for (int nb = 0; nb < 25; nb++) {
            int c = n0w + nb * 8 + 2 * tig;
            float* base = (c < 200) ? mu : ls;
            int cc = (c < 200) ? c : c - 200;
            if (v0) {
                float2 o = make_float2(acc[nb][0] + bias2[nb].x,
                                       acc[nb][1] + bias2[nb].y);
                *(float2*)(base + (long long)r0 * OUTC + cc) = o;
            }
            if (v1) {
                float2 o = make_float2(acc[nb][2] + bias2[nb].x,
                                       acc[nb][3] + bias2[nb].y);
                *(float2*)(base + (long long)r1 * OUTC + cc) = o;
            }
        }
    }
}

// ---------------------------------------------------------------------------
extern "C" void kernel_launch(void* const* d_in, const int* in_sizes, int n_in,
                              void* d_out, int out_size) {
    const float* x  = (const float*)d_in[0];
    const void*  ei = d_in[1];
    const float* W1 = (const float*)d_in[2];
    const float* b1 = (const float*)d_in[3];
    const float* W2 = (const float*)d_in[4];
    const float* b2 = (const float*)d_in[5];
    float*       out = (float*)d_out;

    k_deg_init<<<(NN + 255) / 256, 256>>>((const unsigned*)ei);
    k_deg_count<<<(EE + 255) / 256, 256>>>(ei);
    k_dinv_self<<<(NN * 32 + 255) / 256, 256>>>(x);            // warp/node
    k_scatter<<<(int)(((long long)EE * 32 + 255) / 256), 256>>>(ei, x); // warp/edge

    cudaFuncSetAttribute(k_gemm, cudaFuncAttributeMaxDynamicSharedMemorySize,
                         GEMM_SMEM);
    k_gemm<<<148, 256, GEMM_SMEM>>>(W1, b1, W2, b2, out);
}